// round 1
// baseline (speedup 1.0000x reference)
#include <cuda_runtime.h>
#include <stdint.h>

// ---------------------------------------------------------------------------
// BlurModel: 9x9 box blur -> per-patch sequential threshold search ->
// binarize -> morphological close (9x9 dilate then 9x9 erode), 2048x2048 f32.
//
// Threshold search is reduced to two exact order statistics per patch
// (k-th largest blurred value) + an exact ulp-space simulation of the
// fp32 "t -= 5e-5f / t += 5e-6f" iteration.
// ---------------------------------------------------------------------------

#define W      2048
#define NPX    (W * W)
#define WORDS  64           // 2048 bits / 32
#define NPAT   64
#define NB     65536        // fine histogram bins
#define VLO    0.40f
#define VSC    327680.0f    // NB / 0.2
#define CAP    1024         // candidate list capacity per bin

__device__ float     g_H[NPX];          // horizontal blur sums
__device__ float     g_B[NPX];          // blurred image
__device__ unsigned  g_hist[NPAT * NB]; // per-patch fine histogram
__device__ float     g_vd[NPAT];        // V_desc[C_lo-1] per patch
__device__ float     g_vu[NPAT];        // V_desc[C_hi]   per patch
__device__ float     g_ths[NPAT];       // final thresholds
__device__ unsigned  g_bits0[W * WORDS];
__device__ unsigned  g_bits1[W * WORDS];

// ---------------------------------------------------------------------------
__device__ __forceinline__ int bin_of(float v) {
    float f = (v - VLO) * VSC;
    int b = (int)floorf(f);
    return b < 0 ? 0 : (b > NB - 1 ? NB - 1 : b);
}

// ---------------------------------------------------------------------------
// K1: horizontal 9-sum with zero padding
__global__ void k_hblur(const float* __restrict__ x) {
    int idx = blockIdx.x * blockDim.x + threadIdx.x;
    int r = idx >> 11, c = idx & 2047;
    const float* row = x + (r << 11);
    float s = 0.0f;
#pragma unroll
    for (int d = -4; d <= 4; ++d) {
        int cc = c + d;
        if (cc >= 0 && cc < W) s += row[cc];
    }
    g_H[idx] = s;
}

// K2: vertical 9-sum, scale by blur_k[0], write blurred, build histograms
__global__ void k_vblur_hist(const float* __restrict__ kptr) {
    int idx = blockIdx.x * blockDim.x + threadIdx.x;
    int r = idx >> 11, c = idx & 2047;
    float kf = __ldg(kptr);
    float s = 0.0f;
#pragma unroll
    for (int d = -4; d <= 4; ++d) {
        int rr = r + d;
        if (rr >= 0 && rr < W) s += g_H[(rr << 11) + c];
    }
    float b = s * kf;
    g_B[idx] = b;
    int p = ((r >> 8) << 3) | (c >> 8);
    atomicAdd(&g_hist[p * NB + bin_of(b)], 1u);
}

// ---------------------------------------------------------------------------
// Find bin + within-bin descending rank for global descending rank k.
__device__ void find_bin_rank(const unsigned* __restrict__ hist,
                              const unsigned* __restrict__ segSum,
                              int k, int* obin, int* orank) {
    unsigned S = 0;
    for (int s = 255; s >= 0; --s) {
        unsigned ss = segSum[s];
        if ((unsigned)k < S + ss) {
            int base = s * 256;
            for (int b = base + 255; b >= base; --b) {
                unsigned hb = hist[b];
                if ((unsigned)k < S + hb) { *obin = b; *orank = (int)((unsigned)k - S); return; }
                S += hb;
            }
            *obin = -1; *orank = 0; return;
        }
        S += ss;
    }
    *obin = -1; *orank = 0;
}

// value at descending index k in small array (ties handled, order-independent)
__device__ float kth_largest(const float* a, int n, int k) {
    if (n <= 0) return 0.5f;
    if (k >= n) k = n - 1;
    for (int i = 0; i < n; ++i) {
        float v = a[i];
        int g = 0, e = 0;
        for (int j = 0; j < n; ++j) {
            if (a[j] > v) g++;
            else if (a[j] == v) e++;
        }
        if (g <= k && k < g + e) return v;
    }
    return a[0];
}

// K3: per-patch exact selection of the two critical order statistics
__global__ void k_select() {
    int p = blockIdx.x;
    int t = threadIdx.x;
    const unsigned* hist = g_hist + p * NB;

    __shared__ unsigned segSum[256];
    __shared__ float listD[CAP];
    __shared__ float listU[CAP];
    __shared__ int cntD, cntU;
    __shared__ int s_binD, s_rD, s_binU, s_rU;

    // per-thread segment sums (256 bins each, vectorized)
    unsigned s = 0;
    const uint4* h4 = (const uint4*)(hist + t * 256);
#pragma unroll
    for (int i = 0; i < 64; ++i) {
        uint4 v = h4[i];
        s += v.x + v.y + v.z + v.w;
    }
    segSum[t] = s;
    if (t == 0) { cntD = 0; cntU = 0; }
    __syncthreads();

    if (t == 0) {
        bool frame = (p < 8) || (p >= 56) || ((p & 7) == 0) || ((p & 7) == 7);
        float lo = frame ? (0.47f - 0.05f) : 0.47f;
        float hiT = 0.43f;
        const float inv = 1.0f / 65536.0f;  // exact power of two

        int Clo = (int)ceilf(lo * 65536.0f);
        while ((float)Clo * inv < lo) Clo++;
        while (Clo > 0 && (float)(Clo - 1) * inv >= lo) Clo--;

        int Chi = (int)floorf(hiT * 65536.0f);
        while ((float)(Chi + 1) * inv <= hiT) Chi++;
        while (Chi > 0 && (float)Chi * inv > hiT) Chi--;

        int kd = Clo - 1;   // descending index for down-loop statistic
        int ku = Chi;       // descending index for up-loop statistic
        find_bin_rank(hist, segSum, kd, &s_binD, &s_rD);
        find_bin_rank(hist, segSum, ku, &s_binU, &s_rU);
    }
    __syncthreads();

    int binD = s_binD, binU = s_binU;
    int pr = (p >> 3) << 8, pc = (p & 7) << 8;
    for (int i = t; i < 65536; i += 256) {
        int rr = pr + (i >> 8), cc = pc + (i & 255);
        float v = g_B[(rr << 11) + cc];
        int b = bin_of(v);
        if (b == binD) {
            int pos = atomicAdd(&cntD, 1);
            if (pos < CAP) listD[pos] = v;
        }
        if (binU != binD && b == binU) {
            int pos = atomicAdd(&cntU, 1);
            if (pos < CAP) listU[pos] = v;
        }
    }
    __syncthreads();

    if (t == 0) {
        int nD = cntD < CAP ? cntD : CAP;
        g_vd[p] = kth_largest(listD, nD, s_rD);
        if (binU == binD) {
            g_vu[p] = kth_largest(listD, nD, s_rU);
        } else {
            int nU = cntU < CAP ? cntU : CAP;
            g_vu[p] = kth_largest(listU, nU, s_rU);
        }
    }
}

// ---------------------------------------------------------------------------
// K4: sequential fp32 threshold iteration, exact, with ulp-space jumps.
// In [0.5,1):  t+5e-6f == +84 ulps, t-5e-5f == -839 ulps (frac .886/.861, no ties)
// In [0.25,.5): +168 / -1678 ulps.
__global__ void k_thresh() {
    if (threadIdx.x != 0 || blockIdx.x != 0) return;
    float t = 0.5f;
    for (int p = 0; p < NPAT; ++p) {
        float vd = g_vd[p], vu = g_vu[p];

        // down loop: while frac < lo  <=>  while t >= vd : t -= 5e-5f
        int guard = 0;
        while (t >= vd && guard < 1000000) {
            guard++;
            bool jumped = false;
            if (t >= 0.25f && t < 1.0f) {
                float bandlo = (t >= 0.5f) ? 0.5f : 0.25f;
                int ulps     = (t >= 0.5f) ? 839 : 1678;
                float tgt = fmaxf(vd, bandlo);
                int mt = __float_as_int(t), mv = __float_as_int(tgt);
                int kj = (mt - mv) / ulps - 1;
                if (kj > 0) { t = __int_as_float(mt - kj * ulps); jumped = true; }
            }
            if (!jumped) t = t - 5e-5f;
        }

        // up loop: while frac > hi  <=>  while t < vu : t += 5e-6f
        guard = 0;
        while (t < vu && guard < 2000000) {
            guard++;
            bool jumped = false;
            if (t >= 0.25f && t < 1.0f) {
                float bandhi = (t >= 0.5f) ? 1.0f : 0.5f;
                int ulps     = (t >= 0.5f) ? 84 : 168;
                float tgt = fminf(vu, bandhi);
                int mt = __float_as_int(t), mv = __float_as_int(tgt);
                int kj = (mv - mt) / ulps - 1;
                if (kj > 0) { t = __int_as_float(mt + kj * ulps); jumped = true; }
            }
            if (!jumped) t = t + 5e-6f;
        }
        g_ths[p] = t;
    }
}

// ---------------------------------------------------------------------------
// K5: binarize to bitmask via ballot
__global__ void k_binarize() {
    int idx = blockIdx.x * blockDim.x + threadIdx.x;
    int r = idx >> 11, c = idx & 2047;
    int p = ((r >> 8) << 3) | (c >> 8);
    bool bit = g_B[idx] > g_ths[p];
    unsigned m = __ballot_sync(0xFFFFFFFFu, bit);
    if ((c & 31) == 0) g_bits0[(r << 6) + (c >> 5)] = m;
}

// K6: horizontal dilate (OR window 9, pad 0): bits0 -> bits1
__global__ void k_dilh() {
    int idx = blockIdx.x * blockDim.x + threadIdx.x;
    int r = idx >> 6, w = idx & 63;
    const unsigned* row = g_bits0 + (r << 6);
    unsigned cur = row[w];
    unsigned left  = (w > 0)  ? row[w - 1] : 0u;
    unsigned right = (w < 63) ? row[w + 1] : 0u;
    unsigned long long a = ((unsigned long long)cur << 32) | left;
    unsigned long long b = ((unsigned long long)right << 32) | cur;
    unsigned o = cur;
#pragma unroll
    for (int k = 1; k <= 4; ++k) {
        o |= (unsigned)(a >> (32 - k));
        o |= (unsigned)(b >> k);
    }
    g_bits1[idx] = o;
}

// K7: vertical dilate (OR 9 rows, pad 0): bits1 -> bits0
__global__ void k_dilv() {
    int idx = blockIdx.x * blockDim.x + threadIdx.x;
    int r = idx >> 6, w = idx & 63;
    unsigned o = 0u;
#pragma unroll
    for (int d = -4; d <= 4; ++d) {
        int rr = r + d;
        if (rr >= 0 && rr < W) o |= g_bits1[(rr << 6) + w];
    }
    g_bits0[idx] = o;
}

// K8: horizontal erode (AND window 9, pad 1): bits0 -> bits1
__global__ void k_eroh() {
    int idx = blockIdx.x * blockDim.x + threadIdx.x;
    int r = idx >> 6, w = idx & 63;
    const unsigned* row = g_bits0 + (r << 6);
    unsigned cur = row[w];
    unsigned left  = (w > 0)  ? row[w - 1] : 0xFFFFFFFFu;
    unsigned right = (w < 63) ? row[w + 1] : 0xFFFFFFFFu;
    unsigned long long a = ((unsigned long long)cur << 32) | left;
    unsigned long long b = ((unsigned long long)right << 32) | cur;
    unsigned o = cur;
#pragma unroll
    for (int k = 1; k <= 4; ++k) {
        o &= (unsigned)(a >> (32 - k));
        o &= (unsigned)(b >> k);
    }
    g_bits1[idx] = o;
}

// K9: vertical erode (AND 9 rows, pad 1): bits1 -> bits0
__global__ void k_erov() {
    int idx = blockIdx.x * blockDim.x + threadIdx.x;
    int r = idx >> 6, w = idx & 63;
    unsigned o = 0xFFFFFFFFu;
#pragma unroll
    for (int d = -4; d <= 4; ++d) {
        int rr = r + d;
        if (rr >= 0 && rr < W) o &= g_bits1[(rr << 6) + w];
    }
    g_bits0[idx] = o;
}

// K10: expand bits to f32 output
__global__ void k_expand(float* __restrict__ out) {
    int idx = blockIdx.x * blockDim.x + threadIdx.x;
    int r = idx >> 11, c = idx & 2047;
    unsigned wv = g_bits0[(r << 6) + (c >> 5)];
    out[idx] = ((wv >> (c & 31)) & 1u) ? 1.0f : 0.0f;
}

// ---------------------------------------------------------------------------
extern "C" void kernel_launch(void* const* d_in, const int* in_sizes, int n_in,
                              void* d_out, int out_size) {
    const float* x  = (const float*)d_in[0];
    const float* bk = (const float*)d_in[1];
    float* out = (float*)d_out;

    void* hptr = nullptr;
    cudaGetSymbolAddress(&hptr, g_hist);
    cudaMemsetAsync(hptr, 0, sizeof(unsigned) * NPAT * NB, 0);

    const int TB = 256;
    k_hblur<<<NPX / TB, TB>>>(x);
    k_vblur_hist<<<NPX / TB, TB>>>(bk);
    k_select<<<NPAT, 256>>>();
    k_thresh<<<1, 32>>>();
    k_binarize<<<NPX / TB, TB>>>();
    k_dilh<<<(W * WORDS) / TB, TB>>>();
    k_dilv<<<(W * WORDS) / TB, TB>>>();
    k_eroh<<<(W * WORDS) / TB, TB>>>();
    k_erov<<<(W * WORDS) / TB, TB>>>();
    k_expand<<<NPX / TB, TB>>>(out);
}

// round 2
// speedup vs baseline: 1.2037x; 1.2037x over previous
#include <cuda_runtime.h>
#include <stdint.h>

// ---------------------------------------------------------------------------
// BlurModel: 9x9 box blur -> per-patch sequential threshold search ->
// binarize -> morphological close (9x9 dilate then 9x9 erode), 2048x2048 f32.
//
// R2: fused tiled blur+histogram, 8192-bin histogram, parallel suffix-scan
// selection, shared-prefetch threshold loop, fused bit-morphology kernels.
// ---------------------------------------------------------------------------

#define W      2048
#define NPX    (W * W)
#define WORDS  64            // 2048 bits / 32
#define NPAT   64
#define NB     8192          // fine histogram bins
#define VLO    0.40f
#define VSC    40960.0f      // NB / 0.2
#define CAP    512           // candidate list capacity per bin

#define TILE_R 16            // morphology row-tile
#define SR     (TILE_R + 8)  // with halo

__device__ float     g_B[NPX];          // blurred image
__device__ unsigned  g_hist[NPAT * NB]; // per-patch fine histogram
__device__ float     g_vd[NPAT];        // V_desc[C_lo-1] per patch
__device__ float     g_vu[NPAT];        // V_desc[C_hi]   per patch
__device__ float     g_ths[NPAT];       // final thresholds
__device__ unsigned  g_bitsD[W * WORDS];// after dilate (close stage 1)

// ---------------------------------------------------------------------------
__device__ __forceinline__ int bin_of(float v) {
    float f = (v - VLO) * VSC;
    int b = (int)floorf(f);
    return b < 0 ? 0 : (b > NB - 1 ? NB - 1 : b);
}

// ---------------------------------------------------------------------------
// K1: fused 9x9 separable box blur (same fp order as reference-matching R1)
//     + blurred write + per-patch histogram atomics.
// Tile: 64 cols x 32 rows output, halo 4. 256 threads.
__global__ void k_blur_hist(const float* __restrict__ x,
                            const float* __restrict__ kptr) {
    __shared__ float raw[40][72];
    __shared__ float hs[40][64];
    int c0 = blockIdx.x << 6;   // 0..2047 step 64
    int r0 = blockIdx.y << 5;   // 0..2047 step 32
    int tid = threadIdx.x;
    float kf = __ldg(kptr);

    // load raw tile with zero padding
    for (int i = tid; i < 40 * 72; i += 256) {
        int rr = i / 72, cc = i % 72;
        int gr = r0 - 4 + rr, gc = c0 - 4 + cc;
        float v = 0.0f;
        if (gr >= 0 && gr < W && gc >= 0 && gc < W) v = x[(gr << 11) + gc];
        raw[rr][cc] = v;
    }
    __syncthreads();

    // horizontal 9-sum (order: left to right, matches d=-4..4)
    for (int i = tid; i < 40 * 64; i += 256) {
        int rr = i >> 6, cc = i & 63;
        float s = 0.0f;
#pragma unroll
        for (int k = 0; k < 9; ++k) s += raw[rr][cc + k];
        hs[rr][cc] = s;
    }
    __syncthreads();

    // vertical 9-sum (order: top to bottom, matches d=-4..4), scale, hist
    for (int i = tid; i < 32 * 64; i += 256) {
        int orow = i >> 6, oc = i & 63;
        float s = 0.0f;
#pragma unroll
        for (int k = 0; k < 9; ++k) s += hs[orow + k][oc];
        float b = s * kf;
        int gr = r0 + orow, gc = c0 + oc;
        g_B[(gr << 11) + gc] = b;
        int p = ((gr >> 8) << 3) | (gc >> 8);
        atomicAdd(&g_hist[p * NB + bin_of(b)], 1u);
    }
}

// ---------------------------------------------------------------------------
// small exact selection: value at descending index k (ties ok)
__device__ float kth_largest(const float* a, int n, int k) {
    if (n <= 0) return 0.5f;
    if (k >= n) k = n - 1;
    for (int i = 0; i < n; ++i) {
        float v = a[i];
        int g = 0, e = 0;
        for (int j = 0; j < n; ++j) {
            if (a[j] > v) g++;
            else if (a[j] == v) e++;
        }
        if (g <= k && k < g + e) return v;
    }
    return a[0];
}

// K2: per-patch exact selection of the two critical order statistics.
// 64 blocks x 256 threads. Parallel suffix-scan over 256 segments of 32 bins.
__global__ void k_select() {
    int p = blockIdx.x;
    int t = threadIdx.x;
    const unsigned* hist = g_hist + p * NB;

    __shared__ unsigned seg[256];
    __shared__ unsigned bufA[256];
    __shared__ unsigned bufB[256];
    __shared__ int s_binD, s_rD, s_binU, s_rU;
    __shared__ float listD[CAP];
    __shared__ float listU[CAP];
    __shared__ int cntD, cntU;

    // segment sums: 32 bins per thread (8 x uint4)
    unsigned s = 0;
    const uint4* h4 = (const uint4*)(hist + t * 32);
#pragma unroll
    for (int i = 0; i < 8; ++i) {
        uint4 v = h4[i];
        s += v.x + v.y + v.z + v.w;
    }
    seg[t] = s;
    bufA[t] = s;
    if (t == 0) { cntD = 0; cntU = 0; }
    __syncthreads();

    // inclusive suffix sum over segments (sufIncl[t] = sum_{s>=t} seg[s])
    unsigned* cur = bufA;
    unsigned* nxt = bufB;
#pragma unroll
    for (int off = 1; off < 256; off <<= 1) {
        unsigned v = cur[t] + ((t + off) < 256 ? cur[t + off] : 0u);
        __syncthreads();
        nxt[t] = v;
        __syncthreads();
        unsigned* tmp = cur; cur = nxt; nxt = tmp;
    }

    // compute the two descending ranks (every thread, deterministic)
    bool frame = (p < 8) || (p >= 56) || ((p & 7) == 0) || ((p & 7) == 7);
    float lo = frame ? (0.47f - 0.05f) : 0.47f;
    float hiT = 0.43f;
    const float inv = 1.0f / 65536.0f;
    int Clo = (int)ceilf(lo * 65536.0f);
    while ((float)Clo * inv < lo) Clo++;
    while (Clo > 0 && (float)(Clo - 1) * inv >= lo) Clo--;
    int Chi = (int)floorf(hiT * 65536.0f);
    while ((float)(Chi + 1) * inv <= hiT) Chi++;
    while (Chi > 0 && (float)Chi * inv > hiT) Chi--;
    int kd = Clo - 1;
    int ku = Chi;

    unsigned incl = cur[t];
    unsigned above = incl - seg[t];   // values in higher segments

    if ((unsigned)kd >= above && (unsigned)kd < incl) {
        unsigned S = above;
        for (int b = 31; b >= 0; --b) {
            unsigned hb = hist[t * 32 + b];
            if ((unsigned)kd < S + hb) { s_binD = t * 32 + b; s_rD = (int)((unsigned)kd - S); break; }
            S += hb;
        }
    }
    if ((unsigned)ku >= above && (unsigned)ku < incl) {
        unsigned S = above;
        for (int b = 31; b >= 0; --b) {
            unsigned hb = hist[t * 32 + b];
            if ((unsigned)ku < S + hb) { s_binU = t * 32 + b; s_rU = (int)((unsigned)ku - S); break; }
            S += hb;
        }
    }
    __syncthreads();

    int binD = s_binD, binU = s_binU;
    int pr = (p >> 3) << 8, pc = (p & 7) << 8;
    for (int i = t; i < 65536; i += 256) {
        int rr = pr + (i >> 8), cc = pc + (i & 255);
        float v = g_B[(rr << 11) + cc];
        int b = bin_of(v);
        if (b == binD) {
            int pos = atomicAdd(&cntD, 1);
            if (pos < CAP) listD[pos] = v;
        }
        if (binU != binD && b == binU) {
            int pos = atomicAdd(&cntU, 1);
            if (pos < CAP) listU[pos] = v;
        }
    }
    __syncthreads();

    if (t == 0) {
        int nD = cntD < CAP ? cntD : CAP;
        g_vd[p] = kth_largest(listD, nD, s_rD);
        if (binU == binD) {
            g_vu[p] = kth_largest(listD, nD, s_rU);
        } else {
            int nU = cntU < CAP ? cntU : CAP;
            g_vu[p] = kth_largest(listU, nU, s_rU);
        }
    }
}

// ---------------------------------------------------------------------------
// K3: sequential fp32 threshold iteration, exact, with ulp-space jumps.
// Loads all vd/vu in parallel first (kills serialized DRAM latency).
__global__ void k_thresh() {
    __shared__ float svd[NPAT], svu[NPAT];
    int tid = threadIdx.x;
    if (tid < NPAT) { svd[tid] = g_vd[tid]; svu[tid] = g_vu[tid]; }
    __syncthreads();
    if (tid != 0) return;

    float t = 0.5f;
    for (int p = 0; p < NPAT; ++p) {
        float vd = svd[p], vu = svu[p];

        int guard = 0;
        while (t >= vd && guard < 1000000) {
            guard++;
            bool jumped = false;
            if (t >= 0.25f && t < 1.0f) {
                float bandlo = (t >= 0.5f) ? 0.5f : 0.25f;
                int ulps     = (t >= 0.5f) ? 839 : 1678;
                float tgt = fmaxf(vd, bandlo);
                int mt = __float_as_int(t), mv = __float_as_int(tgt);
                int kj = (mt - mv) / ulps - 1;
                if (kj > 0) { t = __int_as_float(mt - kj * ulps); jumped = true; }
            }
            if (!jumped) t = t - 5e-5f;
        }

        guard = 0;
        while (t < vu && guard < 2000000) {
            guard++;
            bool jumped = false;
            if (t >= 0.25f && t < 1.0f) {
                float bandhi = (t >= 0.5f) ? 1.0f : 0.5f;
                int ulps     = (t >= 0.5f) ? 84 : 168;
                float tgt = fminf(vu, bandhi);
                int mt = __float_as_int(t), mv = __float_as_int(tgt);
                int kj = (mv - mt) / ulps - 1;
                if (kj > 0) { t = __int_as_float(mt + kj * ulps); jumped = true; }
            }
            if (!jumped) t = t + 5e-6f;
        }
        g_ths[p] = t;
    }
}

// ---------------------------------------------------------------------------
// K4: binarize + horizontal dilate + vertical dilate (pad 0), bit-packed.
// 128 blocks x 256 threads; tile = full width x TILE_R rows.
__global__ void k_dil() {
    __shared__ unsigned sb[SR][WORDS];
    __shared__ unsigned dh[SR][WORDS];
    int r0 = blockIdx.x * TILE_R;
    int tid = threadIdx.x;
    int warpId = tid >> 5, lane = tid & 31;

    // binarize SR rows (ballot, warp-uniform loop)
    for (int i = warpId; i < SR * WORDS; i += 8) {
        int row = i >> 6, wc = i & 63;
        int grr = r0 - 4 + row;
        int gc = (wc << 5) + lane;
        bool bit = false;
        if (grr >= 0 && grr < W) {
            int pt = ((grr >> 8) << 3) | (gc >> 8);
            bit = g_B[(grr << 11) + gc] > __ldg(&g_ths[pt]);
        }
        unsigned m = __ballot_sync(0xFFFFFFFFu, bit);
        if (lane == 0) sb[row][wc] = m;
    }
    __syncthreads();

    // horizontal dilate (OR window 9, pad 0)
    for (int i = tid; i < SR * WORDS; i += 256) {
        int row = i >> 6, wc = i & 63;
        unsigned curw = sb[row][wc];
        unsigned left  = (wc > 0)  ? sb[row][wc - 1] : 0u;
        unsigned right = (wc < 63) ? sb[row][wc + 1] : 0u;
        unsigned long long a = ((unsigned long long)curw << 32) | left;
        unsigned long long b = ((unsigned long long)right << 32) | curw;
        unsigned o = curw;
#pragma unroll
        for (int k = 1; k <= 4; ++k) {
            o |= (unsigned)(a >> (32 - k));
            o |= (unsigned)(b >> k);
        }
        dh[row][wc] = o;
    }
    __syncthreads();

    // vertical dilate (OR 9 rows), write packed
    for (int i = tid; i < TILE_R * WORDS; i += 256) {
        int orow = i >> 6, wc = i & 63;
        unsigned o = 0u;
#pragma unroll
        for (int k = 0; k < 9; ++k) o |= dh[orow + k][wc];
        g_bitsD[((r0 + orow) << 6) + wc] = o;
    }
}

// K5: horizontal erode + vertical erode (pad 1) + expand to f32 output.
__global__ void k_ero(float* __restrict__ out) {
    __shared__ unsigned eb[SR][WORDS];
    __shared__ unsigned eh[SR][WORDS];
    int r0 = blockIdx.x * TILE_R;
    int tid = threadIdx.x;

    for (int i = tid; i < SR * WORDS; i += 256) {
        int row = i >> 6, wc = i & 63;
        int grr = r0 - 4 + row;
        eb[row][wc] = (grr >= 0 && grr < W) ? g_bitsD[(grr << 6) + wc] : 0xFFFFFFFFu;
    }
    __syncthreads();

    // horizontal erode (AND window 9, pad 1)
    for (int i = tid; i < SR * WORDS; i += 256) {
        int row = i >> 6, wc = i & 63;
        unsigned curw = eb[row][wc];
        unsigned left  = (wc > 0)  ? eb[row][wc - 1] : 0xFFFFFFFFu;
        unsigned right = (wc < 63) ? eb[row][wc + 1] : 0xFFFFFFFFu;
        unsigned long long a = ((unsigned long long)curw << 32) | left;
        unsigned long long b = ((unsigned long long)right << 32) | curw;
        unsigned o = curw;
#pragma unroll
        for (int k = 1; k <= 4; ++k) {
            o &= (unsigned)(a >> (32 - k));
            o &= (unsigned)(b >> k);
        }
        eh[row][wc] = o;
    }
    __syncthreads();

    // vertical erode into eb rows 0..TILE_R-1 (eb no longer read)
    for (int i = tid; i < TILE_R * WORDS; i += 256) {
        int orow = i >> 6, wc = i & 63;
        unsigned o = 0xFFFFFFFFu;
#pragma unroll
        for (int k = 0; k < 9; ++k) o &= eh[orow + k][wc];
        eb[orow][wc] = o;
    }
    __syncthreads();

    // expand to f32, coalesced
    for (int i = tid; i < TILE_R * W; i += 256) {
        int orow = i >> 11, c = i & 2047;
        unsigned wv = eb[orow][c >> 5];
        out[((r0 + orow) << 11) + c] = ((wv >> (c & 31)) & 1u) ? 1.0f : 0.0f;
    }
}

// ---------------------------------------------------------------------------
extern "C" void kernel_launch(void* const* d_in, const int* in_sizes, int n_in,
                              void* d_out, int out_size) {
    const float* x  = (const float*)d_in[0];
    const float* bk = (const float*)d_in[1];
    float* out = (float*)d_out;

    void* hptr = nullptr;
    cudaGetSymbolAddress(&hptr, g_hist);
    cudaMemsetAsync(hptr, 0, sizeof(unsigned) * NPAT * NB, 0);

    dim3 gblur(W / 64, W / 32);
    k_blur_hist<<<gblur, 256>>>(x, bk);
    k_select<<<NPAT, 256>>>();
    k_thresh<<<1, 64>>>();
    k_dil<<<W / TILE_R, 256>>>();
    k_ero<<<W / TILE_R, 256>>>(out);
}

// round 3
// speedup vs baseline: 1.6781x; 1.3941x over previous
#include <cuda_runtime.h>
#include <stdint.h>

// ---------------------------------------------------------------------------
// BlurModel: 9x9 box blur -> per-patch sequential threshold search ->
// binarize -> morphological close (9x9 dilate then 9x9 erode), 2048x2048 f32.
// R3: latency-bound kernels restructured for MLP (float4 + shfl packing).
// ---------------------------------------------------------------------------

#define W      2048
#define NPX    (W * W)
#define WORDS  64            // 2048 bits / 32
#define NPAT   64
#define NB     8192          // fine histogram bins
#define VLO    0.40f
#define VSC    40960.0f      // NB / 0.2
#define CAP    512           // candidate list capacity per bin

#define TILE_R 16            // erode row-tile
#define SR     (TILE_R + 8)

// dilate kernel tiling: 512 cols x 16 rows per block
#define DTR    16
#define DSRR   (DTR + 8)     // 24 rows with halo
#define DSW    20            // 18 used words (16 + 2 halo), padded to 20

__device__ float     g_B[NPX];          // blurred image
__device__ unsigned  g_hist[NPAT * NB]; // per-patch fine histogram
__device__ float     g_vd[NPAT];        // V_desc[C_lo-1] per patch
__device__ float     g_vu[NPAT];        // V_desc[C_hi]   per patch
__device__ float     g_ths[NPAT];       // final thresholds
__device__ unsigned  g_bitsD[W * WORDS];// after dilate

// ---------------------------------------------------------------------------
__device__ __forceinline__ int bin_of(float v) {
    float f = (v - VLO) * VSC;
    int b = (int)floorf(f);
    return b < 0 ? 0 : (b > NB - 1 ? NB - 1 : b);
}

// ---------------------------------------------------------------------------
// K1: fused 9x9 separable box blur + histogram. Tile 64x32 out, halo 4.
__global__ void k_blur_hist(const float* __restrict__ x,
                            const float* __restrict__ kptr) {
    __shared__ float raw[40][72];
    __shared__ float hs[40][64];
    int c0 = blockIdx.x << 6;
    int r0 = blockIdx.y << 5;
    int tid = threadIdx.x;
    float kf = __ldg(kptr);

    for (int i = tid; i < 40 * 72; i += 256) {
        int rr = i / 72, cc = i % 72;
        int gr = r0 - 4 + rr, gc = c0 - 4 + cc;
        float v = 0.0f;
        if (gr >= 0 && gr < W && gc >= 0 && gc < W) v = x[(gr << 11) + gc];
        raw[rr][cc] = v;
    }
    __syncthreads();

    for (int i = tid; i < 40 * 64; i += 256) {
        int rr = i >> 6, cc = i & 63;
        float s = 0.0f;
#pragma unroll
        for (int k = 0; k < 9; ++k) s += raw[rr][cc + k];
        hs[rr][cc] = s;
    }
    __syncthreads();

    for (int i = tid; i < 32 * 64; i += 256) {
        int orow = i >> 6, oc = i & 63;
        float s = 0.0f;
#pragma unroll
        for (int k = 0; k < 9; ++k) s += hs[orow + k][oc];
        float b = s * kf;
        int gr = r0 + orow, gc = c0 + oc;
        g_B[(gr << 11) + gc] = b;
        int p = ((gr >> 8) << 3) | (gc >> 8);
        atomicAdd(&g_hist[p * NB + bin_of(b)], 1u);
    }
}

// ---------------------------------------------------------------------------
__device__ float kth_largest(const float* a, int n, int k) {
    if (n <= 0) return 0.5f;
    if (k >= n) k = n - 1;
    for (int i = 0; i < n; ++i) {
        float v = a[i];
        int g = 0, e = 0;
        for (int j = 0; j < n; ++j) {
            if (a[j] > v) g++;
            else if (a[j] == v) e++;
        }
        if (g <= k && k < g + e) return v;
    }
    return a[0];
}

// K2: per-patch exact selection of two order statistics. 64 blocks x 1024 thr.
__global__ void k_select() {
    int p = blockIdx.x;
    int t = threadIdx.x;
    const unsigned* hist = g_hist + p * NB;

    __shared__ unsigned seg[1024];
    __shared__ unsigned bufA[1024];
    __shared__ unsigned bufB[1024];
    __shared__ int s_binD, s_rD, s_binU, s_rU;
    __shared__ float listD[CAP];
    __shared__ float listU[CAP];
    __shared__ int cntD, cntU;

    // segment sums: 8 bins per thread
    const uint4* h4 = (const uint4*)(hist + t * 8);
    uint4 a0 = h4[0], a1 = h4[1];
    unsigned s = a0.x + a0.y + a0.z + a0.w + a1.x + a1.y + a1.z + a1.w;
    seg[t] = s;
    bufA[t] = s;
    if (t == 0) { cntD = 0; cntU = 0; }
    __syncthreads();

    // inclusive suffix sum over 1024 segments
    unsigned* cur = bufA;
    unsigned* nxt = bufB;
#pragma unroll
    for (int off = 1; off < 1024; off <<= 1) {
        unsigned v = cur[t] + ((t + off) < 1024 ? cur[t + off] : 0u);
        __syncthreads();
        nxt[t] = v;
        __syncthreads();
        unsigned* tmp = cur; cur = nxt; nxt = tmp;
    }

    bool frame = (p < 8) || (p >= 56) || ((p & 7) == 0) || ((p & 7) == 7);
    float lo = frame ? (0.47f - 0.05f) : 0.47f;
    float hiT = 0.43f;
    const float inv = 1.0f / 65536.0f;
    int Clo = (int)ceilf(lo * 65536.0f);
    while ((float)Clo * inv < lo) Clo++;
    while (Clo > 0 && (float)(Clo - 1) * inv >= lo) Clo--;
    int Chi = (int)floorf(hiT * 65536.0f);
    while ((float)(Chi + 1) * inv <= hiT) Chi++;
    while (Chi > 0 && (float)Chi * inv > hiT) Chi--;
    int kd = Clo - 1;
    int ku = Chi;

    unsigned incl = cur[t];
    unsigned above = incl - seg[t];

    if ((unsigned)kd >= above && (unsigned)kd < incl) {
        unsigned S = above;
        for (int b = 7; b >= 0; --b) {
            unsigned hb = hist[t * 8 + b];
            if ((unsigned)kd < S + hb) { s_binD = t * 8 + b; s_rD = (int)((unsigned)kd - S); break; }
            S += hb;
        }
    }
    if ((unsigned)ku >= above && (unsigned)ku < incl) {
        unsigned S = above;
        for (int b = 7; b >= 0; --b) {
            unsigned hb = hist[t * 8 + b];
            if ((unsigned)ku < S + hb) { s_binU = t * 8 + b; s_rU = (int)((unsigned)ku - S); break; }
            S += hb;
        }
    }
    __syncthreads();

    int binD = s_binD, binU = s_binU;
    int pr = (p >> 3) << 8, pc = (p & 7) << 8;
    const float4* B4 = (const float4*)g_B;
    for (int i = t; i < 16384; i += 1024) {
        int rr = pr + (i >> 6);
        int cc = pc + ((i & 63) << 2);
        float4 v = B4[((rr << 11) + cc) >> 2];
        float vv[4] = {v.x, v.y, v.z, v.w};
#pragma unroll
        for (int q = 0; q < 4; ++q) {
            int b = bin_of(vv[q]);
            if (b == binD) {
                int pos = atomicAdd(&cntD, 1);
                if (pos < CAP) listD[pos] = vv[q];
            }
            if (binU != binD && b == binU) {
                int pos = atomicAdd(&cntU, 1);
                if (pos < CAP) listU[pos] = vv[q];
            }
        }
    }
    __syncthreads();

    if (t == 0) {
        int nD = cntD < CAP ? cntD : CAP;
        g_vd[p] = kth_largest(listD, nD, s_rD);
        if (binU == binD) {
            g_vu[p] = kth_largest(listD, nD, s_rU);
        } else {
            int nU = cntU < CAP ? cntU : CAP;
            g_vu[p] = kth_largest(listU, nU, s_rU);
        }
    }
}

// ---------------------------------------------------------------------------
// K3: sequential fp32 threshold iteration, exact ulp-space jumps.
__global__ void k_thresh() {
    __shared__ float svd[NPAT], svu[NPAT];
    int tid = threadIdx.x;
    if (tid < NPAT) { svd[tid] = g_vd[tid]; svu[tid] = g_vu[tid]; }
    __syncthreads();
    if (tid != 0) return;

    float t = 0.5f;
    for (int p = 0; p < NPAT; ++p) {
        float vd = svd[p], vu = svu[p];

        int guard = 0;
        while (t >= vd && guard < 1000000) {
            guard++;
            bool jumped = false;
            if (t >= 0.25f && t < 1.0f) {
                float bandlo = (t >= 0.5f) ? 0.5f : 0.25f;
                int ulps     = (t >= 0.5f) ? 839 : 1678;
                float tgt = fmaxf(vd, bandlo);
                int mt = __float_as_int(t), mv = __float_as_int(tgt);
                int kj = (mt - mv) / ulps - 1;
                if (kj > 0) { t = __int_as_float(mt - kj * ulps); jumped = true; }
            }
            if (!jumped) t = t - 5e-5f;
        }

        guard = 0;
        while (t < vu && guard < 2000000) {
            guard++;
            bool jumped = false;
            if (t >= 0.25f && t < 1.0f) {
                float bandhi = (t >= 0.5f) ? 1.0f : 0.5f;
                int ulps     = (t >= 0.5f) ? 84 : 168;
                float tgt = fminf(vu, bandhi);
                int mt = __float_as_int(t), mv = __float_as_int(tgt);
                int kj = (mv - mt) / ulps - 1;
                if (kj > 0) { t = __int_as_float(mt + kj * ulps); jumped = true; }
            }
            if (!jumped) t = t + 5e-6f;
        }
        g_ths[p] = t;
    }
}

// ---------------------------------------------------------------------------
// K4: binarize + 9x9 dilate (pad 0), bit-packed.
// Grid (4, 128): tile 512 cols x 16 rows. 256 threads.
// Binarize: float4 per lane (coalesced 512B/warp), word assembly via shfl_xor.
__global__ void k_dil() {
    __shared__ unsigned sb[DSRR][DSW];
    __shared__ unsigned dh[DSRR][16];
    __shared__ float sth[NPAT];
    int wbase = blockIdx.x << 4;         // first output word (16 words = 512 px)
    int r0 = blockIdx.y * DTR;
    int tid = threadIdx.x;
    int warpId = tid >> 5, lane = tid & 31;

    if (tid < NPAT) sth[tid] = g_ths[tid];
    __syncthreads();

    // warp-task: 128 px (32 lanes x float4) = 4 words of one tile row.
    // tasks: DSRR rows x 5 quad-words (covers 20 words; words 18,19 are pad)
#pragma unroll 2
    for (int tsk = warpId; tsk < DSRR * 5; tsk += 8) {
        int row = tsk / 5, qw = tsk - row * 5;
        int tw = (qw << 2) + (lane >> 3);          // tile word 0..19
        int gw = wbase - 1 + tw;                   // global word
        int gr = r0 - 4 + row;
        int gc = (gw << 5) + ((lane & 7) << 2);
        unsigned nib = 0;
        if (gr >= 0 && gr < W && gw >= 0 && gw < WORDS) {
            float th = sth[((gr >> 8) << 3) | (gw >> 3)];
            const float4* rp = (const float4*)(g_B + (gr << 11));
            float4 v = rp[gc >> 2];
            nib = (unsigned)(v.x > th) | ((unsigned)(v.y > th) << 1)
                | ((unsigned)(v.z > th) << 2) | ((unsigned)(v.w > th) << 3);
        }
        // merge nibbles -> 32-bit word held by lanes with (lane&7)==0
        unsigned x = nib | (__shfl_xor_sync(0xFFFFFFFFu, nib, 1) << 4);
        x = x | (__shfl_xor_sync(0xFFFFFFFFu, x, 2) << 8);
        x = x | (__shfl_xor_sync(0xFFFFFFFFu, x, 4) << 16);
        if ((lane & 7) == 0) sb[row][tw] = x;
    }
    __syncthreads();

    // horizontal dilate: output words 0..15 use sb words 0..17
    for (int i = tid; i < DSRR * 16; i += 256) {
        int row = i >> 4, ow = i & 15;
        unsigned curw = sb[row][ow + 1];
        unsigned left = sb[row][ow];
        unsigned right = sb[row][ow + 2];
        unsigned long long a = ((unsigned long long)curw << 32) | left;
        unsigned long long b = ((unsigned long long)right << 32) | curw;
        unsigned o = curw;
#pragma unroll
        for (int k = 1; k <= 4; ++k) {
            o |= (unsigned)(a >> (32 - k));
            o |= (unsigned)(b >> k);
        }
        dh[row][ow] = o;
    }
    __syncthreads();

    // vertical dilate, write packed
    {
        int orow = tid >> 4, ow = tid & 15;   // 256 = 16x16
        unsigned o = 0u;
#pragma unroll
        for (int k = 0; k < 9; ++k) o |= dh[orow + k][ow];
        g_bitsD[((r0 + orow) << 6) + wbase + ow] = o;
    }
}

// K5: 9x9 erode (pad 1) + expand to f32 (float4 stores).
__global__ void k_ero(float* __restrict__ out) {
    __shared__ unsigned eb[SR][WORDS];
    __shared__ unsigned eh[SR][WORDS];
    int r0 = blockIdx.x * TILE_R;
    int tid = threadIdx.x;

    for (int i = tid; i < SR * WORDS; i += 256) {
        int row = i >> 6, wc = i & 63;
        int grr = r0 - 4 + row;
        eb[row][wc] = (grr >= 0 && grr < W) ? g_bitsD[(grr << 6) + wc] : 0xFFFFFFFFu;
    }
    __syncthreads();

    for (int i = tid; i < SR * WORDS; i += 256) {
        int row = i >> 6, wc = i & 63;
        unsigned curw = eb[row][wc];
        unsigned left  = (wc > 0)  ? eb[row][wc - 1] : 0xFFFFFFFFu;
        unsigned right = (wc < 63) ? eb[row][wc + 1] : 0xFFFFFFFFu;
        unsigned long long a = ((unsigned long long)curw << 32) | left;
        unsigned long long b = ((unsigned long long)right << 32) | curw;
        unsigned o = curw;
#pragma unroll
        for (int k = 1; k <= 4; ++k) {
            o &= (unsigned)(a >> (32 - k));
            o &= (unsigned)(b >> k);
        }
        eh[row][wc] = o;
    }
    __syncthreads();

    for (int i = tid; i < TILE_R * WORDS; i += 256) {
        int orow = i >> 6, wc = i & 63;
        unsigned o = 0xFFFFFFFFu;
#pragma unroll
        for (int k = 0; k < 9; ++k) o &= eh[orow + k][wc];
        eb[orow][wc] = o;
    }
    __syncthreads();

    float4* out4 = (float4*)out;
    for (int i = tid; i < TILE_R * 512; i += 256) {
        int orow = i >> 9;
        int c = (i & 511) << 2;
        unsigned wv = eb[orow][c >> 5];
        int sh = c & 31;
        float4 o;
        o.x = ((wv >> (sh + 0)) & 1u) ? 1.0f : 0.0f;
        o.y = ((wv >> (sh + 1)) & 1u) ? 1.0f : 0.0f;
        o.z = ((wv >> (sh + 2)) & 1u) ? 1.0f : 0.0f;
        o.w = ((wv >> (sh + 3)) & 1u) ? 1.0f : 0.0f;
        out4[(((r0 + orow) << 11) + c) >> 2] = o;
    }
}

// ---------------------------------------------------------------------------
extern "C" void kernel_launch(void* const* d_in, const int* in_sizes, int n_in,
                              void* d_out, int out_size) {
    const float* x  = (const float*)d_in[0];
    const float* bk = (const float*)d_in[1];
    float* out = (float*)d_out;

    void* hptr = nullptr;
    cudaGetSymbolAddress(&hptr, g_hist);
    cudaMemsetAsync(hptr, 0, sizeof(unsigned) * NPAT * NB, 0);

    dim3 gblur(W / 64, W / 32);
    k_blur_hist<<<gblur, 256>>>(x, bk);
    k_select<<<NPAT, 1024>>>();
    k_thresh<<<1, 64>>>();
    dim3 gdil(4, W / DTR);
    k_dil<<<gdil, 256>>>();
    k_ero<<<W / TILE_R, 256>>>(out);
}

// round 5
// speedup vs baseline: 1.9190x; 1.1435x over previous
#include <cuda_runtime.h>
#include <stdint.h>

// ---------------------------------------------------------------------------
// BlurModel: 9x9 box blur -> per-patch sequential threshold search ->
// binarize -> morphological close, 2048x2048 f32.
// R5: R4 with warp-shuffle suffix scan (fits 48KB static smem).
// ---------------------------------------------------------------------------

#define W      2048
#define NPX    (W * W)
#define WORDS  64
#define NPAT   64
#define NB     8192
#define VLO    0.40f
#define VSC    40960.0f      // NB / 0.2
#define CAP    512

__device__ float g_B[NPX];
__device__ float g_vd[NPAT];
__device__ float g_vu[NPAT];
__device__ float g_ths[NPAT];

// ---------------------------------------------------------------------------
__device__ __forceinline__ int bin_of(float v) {
    float f = (v - VLO) * VSC;
    int b = (int)floorf(f);
    return b < 0 ? 0 : (b > NB - 1 ? NB - 1 : b);
}

// ---------------------------------------------------------------------------
// K1: fused 9x9 separable box blur. Tile 64x32 out, halo 4. 256 threads.
__global__ void k_blur(const float* __restrict__ x,
                       const float* __restrict__ kptr) {
    __shared__ float raw[40][72];
    __shared__ float hs[40][64];
    int c0 = blockIdx.x << 6;
    int r0 = blockIdx.y << 5;
    int tid = threadIdx.x;
    float kf = __ldg(kptr);

    for (int i = tid; i < 40 * 72; i += 256) {
        int rr = i / 72, cc = i % 72;
        int gr = r0 - 4 + rr, gc = c0 - 4 + cc;
        float v = 0.0f;
        if (gr >= 0 && gr < W && gc >= 0 && gc < W) v = x[(gr << 11) + gc];
        raw[rr][cc] = v;
    }
    __syncthreads();

    for (int i = tid; i < 40 * 64; i += 256) {
        int rr = i >> 6, cc = i & 63;
        float s = 0.0f;
#pragma unroll
        for (int k = 0; k < 9; ++k) s += raw[rr][cc + k];
        hs[rr][cc] = s;
    }
    __syncthreads();

    for (int i = tid; i < 32 * 64; i += 256) {
        int orow = i >> 6, oc = i & 63;
        float s = 0.0f;
#pragma unroll
        for (int k = 0; k < 9; ++k) s += hs[orow + k][oc];
        int gr = r0 + orow, gc = c0 + oc;
        g_B[(gr << 11) + gc] = s * kf;
    }
}

// ---------------------------------------------------------------------------
__device__ float kth_largest(const float* a, int n, int k) {
    if (n <= 0) return 0.5f;
    if (k >= n) k = n - 1;
    for (int i = 0; i < n; ++i) {
        float v = a[i];
        int g = 0, e = 0;
        for (int j = 0; j < n; ++j) {
            if (a[j] > v) g++;
            else if (a[j] == v) e++;
        }
        if (g <= k && k < g + e) return v;
    }
    return a[0];
}

// K2: per-patch order statistics via SHARED histogram. 64 blocks x 1024 thr.
// Suffix scan done with warp shuffles (no ping-pong buffers).
__global__ void k_select() {
    int p = blockIdx.x;
    int t = threadIdx.x;
    int lane = t & 31, wid = t >> 5;

    __shared__ unsigned hist[NB];          // 32 KB
    __shared__ unsigned seg[1024];         // 4 KB
    __shared__ unsigned warpSuf[32];       // suffix of warp totals (exclusive)
    __shared__ int s_binD, s_rD, s_binU, s_rU;
    __shared__ float listD[CAP];
    __shared__ float listU[CAP];
    __shared__ int cntD, cntU;

#pragma unroll
    for (int i = 0; i < NB / 1024; ++i) hist[t + i * 1024] = 0u;
    if (t == 0) { cntD = 0; cntU = 0; }
    __syncthreads();

    int pr = (p >> 3) << 8, pc = (p & 7) << 8;
    const float4* B4 = (const float4*)g_B;

    // pass 1: build histogram (shared atomics)
    for (int i = t; i < 16384; i += 1024) {
        int rr = pr + (i >> 6);
        int cc = pc + ((i & 63) << 2);
        float4 v = B4[((rr << 11) + cc) >> 2];
        atomicAdd(&hist[bin_of(v.x)], 1u);
        atomicAdd(&hist[bin_of(v.y)], 1u);
        atomicAdd(&hist[bin_of(v.z)], 1u);
        atomicAdd(&hist[bin_of(v.w)], 1u);
    }
    __syncthreads();

    // segment sums: 8 bins per thread
    unsigned segv = 0;
#pragma unroll
    for (int b = 0; b < 8; ++b) segv += hist[t * 8 + b];
    seg[t] = segv;

    // warp-level inclusive suffix sum of segv
    unsigned suf = segv;
#pragma unroll
    for (int off = 1; off < 32; off <<= 1) {
        unsigned v = __shfl_down_sync(0xFFFFFFFFu, suf, off);
        if (lane + off < 32) suf += v;
    }
    // warp total = suffix at lane 0
    unsigned wtot = __shfl_sync(0xFFFFFFFFu, suf, 0);
    if (lane == 0) warpSuf[wid] = wtot;     // temporarily totals
    __syncthreads();
    // warp 0 converts totals -> exclusive suffix (sum of totals of warps > w)
    if (wid == 0) {
        unsigned tot = warpSuf[lane];
        unsigned ss = tot;
#pragma unroll
        for (int off = 1; off < 32; off <<= 1) {
            unsigned v = __shfl_down_sync(0xFFFFFFFFu, ss, off);
            if (lane + off < 32) ss += v;
        }
        warpSuf[lane] = ss - tot;           // exclusive
    }
    __syncthreads();

    unsigned incl = suf + warpSuf[wid];     // sum over segments >= t
    unsigned above = incl - segv;

    bool frame = (p < 8) || (p >= 56) || ((p & 7) == 0) || ((p & 7) == 7);
    float lo = frame ? (0.47f - 0.05f) : 0.47f;
    float hiT = 0.43f;
    const float inv = 1.0f / 65536.0f;
    int Clo = (int)ceilf(lo * 65536.0f);
    while ((float)Clo * inv < lo) Clo++;
    while (Clo > 0 && (float)(Clo - 1) * inv >= lo) Clo--;
    int Chi = (int)floorf(hiT * 65536.0f);
    while ((float)(Chi + 1) * inv <= hiT) Chi++;
    while (Chi > 0 && (float)Chi * inv > hiT) Chi--;
    int kd = Clo - 1;
    int ku = Chi;

    if ((unsigned)kd >= above && (unsigned)kd < incl) {
        unsigned S = above;
        for (int b = 7; b >= 0; --b) {
            unsigned hb = hist[t * 8 + b];
            if ((unsigned)kd < S + hb) { s_binD = t * 8 + b; s_rD = (int)((unsigned)kd - S); break; }
            S += hb;
        }
    }
    if ((unsigned)ku >= above && (unsigned)ku < incl) {
        unsigned S = above;
        for (int b = 7; b >= 0; --b) {
            unsigned hb = hist[t * 8 + b];
            if ((unsigned)ku < S + hb) { s_binU = t * 8 + b; s_rU = (int)((unsigned)ku - S); break; }
            S += hb;
        }
    }
    __syncthreads();

    // pass 2: collect candidate values of the two bins (L2-resident reads)
    int binD = s_binD, binU = s_binU;
    for (int i = t; i < 16384; i += 1024) {
        int rr = pr + (i >> 6);
        int cc = pc + ((i & 63) << 2);
        float4 v = B4[((rr << 11) + cc) >> 2];
        float vv[4] = {v.x, v.y, v.z, v.w};
#pragma unroll
        for (int q = 0; q < 4; ++q) {
            int b = bin_of(vv[q]);
            if (b == binD) {
                int pos = atomicAdd(&cntD, 1);
                if (pos < CAP) listD[pos] = vv[q];
            }
            if (binU != binD && b == binU) {
                int pos = atomicAdd(&cntU, 1);
                if (pos < CAP) listU[pos] = vv[q];
            }
        }
    }
    __syncthreads();

    if (t == 0) {
        int nD = cntD < CAP ? cntD : CAP;
        g_vd[p] = kth_largest(listD, nD, s_rD);
        if (binU == binD) {
            g_vu[p] = kth_largest(listD, nD, s_rU);
        } else {
            int nU = cntU < CAP ? cntU : CAP;
            g_vu[p] = kth_largest(listU, nU, s_rU);
        }
    }
}

// ---------------------------------------------------------------------------
// K3: sequential fp32 threshold iteration, exact ulp-space jumps.
__global__ void k_thresh() {
    __shared__ float svd[NPAT], svu[NPAT];
    int tid = threadIdx.x;
    if (tid < NPAT) { svd[tid] = g_vd[tid]; svu[tid] = g_vu[tid]; }
    __syncthreads();
    if (tid != 0) return;

    float t = 0.5f;
    for (int p = 0; p < NPAT; ++p) {
        float vd = svd[p], vu = svu[p];

        int guard = 0;
        while (t >= vd && guard < 1000000) {
            guard++;
            bool jumped = false;
            if (t >= 0.25f && t < 1.0f) {
                float bandlo = (t >= 0.5f) ? 0.5f : 0.25f;
                int ulps     = (t >= 0.5f) ? 839 : 1678;
                float tgt = fmaxf(vd, bandlo);
                int mt = __float_as_int(t), mv = __float_as_int(tgt);
                int kj = (mt - mv) / ulps - 1;
                if (kj > 0) { t = __int_as_float(mt - kj * ulps); jumped = true; }
            }
            if (!jumped) t = t - 5e-5f;
        }

        guard = 0;
        while (t < vu && guard < 2000000) {
            guard++;
            bool jumped = false;
            if (t >= 0.25f && t < 1.0f) {
                float bandhi = (t >= 0.5f) ? 1.0f : 0.5f;
                int ulps     = (t >= 0.5f) ? 84 : 168;
                float tgt = fminf(vu, bandhi);
                int mt = __float_as_int(t), mv = __float_as_int(tgt);
                int kj = (mv - mt) / ulps - 1;
                if (kj > 0) { t = __int_as_float(mt + kj * ulps); jumped = true; }
            }
            if (!jumped) t = t + 5e-6f;
        }
        g_ths[p] = t;
    }
}

// ---------------------------------------------------------------------------
// K4: fully fused close: binarize + dilH + dilV + eroH + eroV + f32 expand.
// Grid (4, 128): tile 512 cols x 16 rows. 256 threads.
__global__ void k_close(float* __restrict__ out) {
    __shared__ unsigned sbin[32][20];
    __shared__ unsigned sdh[32][20];   // dilH, 18 used
    __shared__ unsigned sdv[24][20];   // dilV, 18 used
    __shared__ unsigned seh[24][16];   // eroH
    __shared__ unsigned sfw[16][16];   // final words
    __shared__ float sth[NPAT];
    int wbase = blockIdx.x << 4;
    int r0 = blockIdx.y << 4;
    int tid = threadIdx.x;
    int warpId = tid >> 5, lane = tid & 31;

    if (tid < NPAT) sth[tid] = g_ths[tid];
    __syncthreads();

    // binarize 32 rows x 20 words: warp task = 4 words of one row (float4/lane)
#pragma unroll 2
    for (int tsk = warpId; tsk < 32 * 5; tsk += 8) {
        int row = tsk / 5, qw = tsk - row * 5;
        int tw = (qw << 2) + (lane >> 3);        // 0..19
        int gw = wbase - 2 + tw;
        int gr = r0 - 8 + row;
        unsigned nib = 0;
        if (gr >= 0 && gr < W && gw >= 0 && gw < WORDS) {
            float th = sth[((gr >> 8) << 3) | (gw >> 3)];
            const float4* rp = (const float4*)(g_B + (gr << 11));
            float4 v = rp[(gw << 3) + (lane & 7)];
            nib = (unsigned)(v.x > th) | ((unsigned)(v.y > th) << 1)
                | ((unsigned)(v.z > th) << 2) | ((unsigned)(v.w > th) << 3);
        }
        unsigned x = nib | (__shfl_xor_sync(0xFFFFFFFFu, nib, 1) << 4);
        x = x | (__shfl_xor_sync(0xFFFFFFFFu, x, 2) << 8);
        x = x | (__shfl_xor_sync(0xFFFFFFFFu, x, 4) << 16);
        if ((lane & 7) == 0) sbin[row][tw] = x;
    }
    __syncthreads();

    // horizontal dilate (pad 0): dh word j (global wbase-1+j), j=0..17
    for (int i = tid; i < 32 * 18; i += 256) {
        int row = i / 18, j = i - row * 18;
        unsigned curw = sbin[row][j + 1];
        unsigned left = sbin[row][j];
        unsigned right = sbin[row][j + 2];
        unsigned long long a = ((unsigned long long)curw << 32) | left;
        unsigned long long b = ((unsigned long long)right << 32) | curw;
        unsigned o = curw;
#pragma unroll
        for (int k = 1; k <= 4; ++k) {
            o |= (unsigned)(a >> (32 - k));
            o |= (unsigned)(b >> k);
        }
        sdh[row][j] = o;
    }
    __syncthreads();

    // vertical dilate (pad 0): dv row dr (global r0-4+dr), dr=0..23
    for (int i = tid; i < 24 * 18; i += 256) {
        int dr = i / 18, j = i - dr * 18;
        unsigned o = 0u;
#pragma unroll
        for (int k = 0; k < 9; ++k) o |= sdh[dr + k][j];
        sdv[dr][j] = o;
    }
    __syncthreads();

    // horizontal erode (pad 1 outside image): out word ow (global wbase+ow)
    for (int i = tid; i < 24 * 16; i += 256) {
        int dr = i >> 4, ow = i & 15;
        unsigned curw = sdv[dr][ow + 1];
        unsigned left  = (wbase + ow - 1 >= 0)    ? sdv[dr][ow]     : 0xFFFFFFFFu;
        unsigned right = (wbase + ow + 1 < WORDS) ? sdv[dr][ow + 2] : 0xFFFFFFFFu;
        unsigned long long a = ((unsigned long long)curw << 32) | left;
        unsigned long long b = ((unsigned long long)right << 32) | curw;
        unsigned o = curw;
#pragma unroll
        for (int k = 1; k <= 4; ++k) {
            o &= (unsigned)(a >> (32 - k));
            o &= (unsigned)(b >> k);
        }
        seh[dr][ow] = o;
    }
    __syncthreads();

    // vertical erode (pad 1 outside image): out rows 0..15
    {
        int orow = tid >> 4, ow = tid & 15;   // 256 = 16x16
        unsigned o = 0xFFFFFFFFu;
#pragma unroll
        for (int k = 0; k < 9; ++k) {
            int gr = r0 + orow - 4 + k;
            unsigned v = (gr >= 0 && gr < W) ? seh[orow + k][ow] : 0xFFFFFFFFu;
            o &= v;
        }
        sfw[orow][ow] = o;
    }
    __syncthreads();

    // expand to f32, float4 stores
    float4* out4 = (float4*)out;
    for (int i = tid; i < 16 * 128; i += 256) {
        int orow = i >> 7;
        int q = i & 127;                 // quad index within 512 cols
        int c = q << 2;
        unsigned wv = sfw[orow][c >> 5];
        int sh = c & 31;
        float4 o;
        o.x = ((wv >> (sh + 0)) & 1u) ? 1.0f : 0.0f;
        o.y = ((wv >> (sh + 1)) & 1u) ? 1.0f : 0.0f;
        o.z = ((wv >> (sh + 2)) & 1u) ? 1.0f : 0.0f;
        o.w = ((wv >> (sh + 3)) & 1u) ? 1.0f : 0.0f;
        out4[(((r0 + orow) << 11) + (wbase << 5) + c) >> 2] = o;
    }
}

// ---------------------------------------------------------------------------
extern "C" void kernel_launch(void* const* d_in, const int* in_sizes, int n_in,
                              void* d_out, int out_size) {
    const float* x  = (const float*)d_in[0];
    const float* bk = (const float*)d_in[1];
    float* out = (float*)d_out;

    dim3 gblur(W / 64, W / 32);
    k_blur<<<gblur, 256>>>(x, bk);
    k_select<<<NPAT, 1024>>>();
    k_thresh<<<1, 64>>>();
    dim3 gclose(4, W / 16);
    k_close<<<gclose, 256>>>(out);
}